// round 2
// baseline (speedup 1.0000x reference)
#include <cuda_runtime.h>
#include <cstdint>

// SubsurfaceFlowTerm: 3 tiny MLPs (4->6->6->1, tanh) -> sigmoid-affine params
// (S1max, ks, n) -> clip(ks*(S1/S1max)^n, 0, S1max).  N = 2,000,000 rows.
//
// R2: packed fma.rn.f32x2 (2 rows per 64-bit lane, 2 lanes per thread),
// weights duplicated in shared so LDS.64 feeds FFMA2 directly,
// sigmoid folded into tanh (1 MUFU), TPB=128 for occupancy.

#define RPT 4            // rows per thread (2 packed pairs)
#define TPB 128

// ---------- packed f32x2 helpers ----------
__device__ __forceinline__ uint64_t pack2(float lo, float hi) {
    uint64_t r;
    asm("mov.b64 %0, {%1, %2};" : "=l"(r) : "f"(lo), "f"(hi));
    return r;
}
__device__ __forceinline__ void unpack2(uint64_t v, float& lo, float& hi) {
    asm("mov.b64 {%0, %1}, %2;" : "=f"(lo), "=f"(hi) : "l"(v));
}
__device__ __forceinline__ uint64_t fma2(uint64_t a, uint64_t b, uint64_t c) {
    uint64_t d;
    asm("fma.rn.f32x2 %0, %1, %2, %3;" : "=l"(d) : "l"(a), "l"(b), "l"(c));
    return d;
}
__device__ __forceinline__ uint64_t mul2(uint64_t a, uint64_t b) {
    uint64_t d;
    asm("mul.rn.f32x2 %0, %1, %2;" : "=l"(d) : "l"(a), "l"(b));
    return d;
}

__device__ __forceinline__ float tanh_fast(float x) {
    float y;
    asm("tanh.approx.f32 %0, %1;" : "=f"(y) : "f"(x));
    return y;
}
__device__ __forceinline__ uint64_t tanh2(uint64_t v) {
    float lo, hi;
    unpack2(v, lo, hi);
    return pack2(tanh_fast(lo), tanh_fast(hi));
}
__device__ __forceinline__ float rcp_fast(float x) {
    float y;
    asm("rcp.approx.f32 %0, %1;" : "=f"(y) : "f"(x));
    return y;
}

__global__ void __launch_bounds__(TPB)
subsurface_flow_kernel(const float4* __restrict__ x4,   // [N] rows of 4
                       const float*  __restrict__ S1,   // [N]
                       const float*  __restrict__ W1,   // [3,4,6]
                       const float*  __restrict__ b1,   // [3,6]
                       const float*  __restrict__ W2,   // [3,6,6]
                       const float*  __restrict__ b2,   // [3,6]
                       const float*  __restrict__ W3,   // [3,6,1]
                       const float*  __restrict__ b3,   // [3,1]
                       float* __restrict__ out,         // [N]
                       int n, int gstride)
{
    // Weights duplicated into both halves of a 64-bit word so a single
    // broadcast LDS.64 is a ready FFMA2 operand.
    __shared__ uint64_t sW1[72];   // k*24 + d*6 + w
    __shared__ uint64_t sb1[18];   // k*6 + w
    __shared__ uint64_t sW2[108];  // k*36 + w*6 + v
    __shared__ uint64_t sb2[18];   // k*6 + v
    __shared__ uint64_t sW3[18];   // k*6 + v
    __shared__ uint64_t sb3[3];    // k

    const int tid = threadIdx.x;
    for (int i = tid; i < 72;  i += TPB) { float w = W1[i]; sW1[i] = pack2(w, w); }
    for (int i = tid; i < 18;  i += TPB) { float w = b1[i]; sb1[i] = pack2(w, w); }
    for (int i = tid; i < 108; i += TPB) { float w = W2[i]; sW2[i] = pack2(w, w); }
    for (int i = tid; i < 18;  i += TPB) { float w = b2[i]; sb2[i] = pack2(w, w); }
    for (int i = tid; i < 18;  i += TPB) { float w = W3[i]; sW3[i] = pack2(w, w); }
    for (int i = tid; i < 3;   i += TPB) { float w = b3[i]; sb3[i] = pack2(w, w); }
    __syncthreads();

    const int t = blockIdx.x * TPB + tid;

    // Load 4 rows (coalesced), pack into 2 f32x2 lanes: pair p = rows (2p, 2p+1)
    float s1v[RPT];
    int   row[RPT];
    bool  valid[RPT];
    float xv[RPT][4];
#pragma unroll
    for (int j = 0; j < RPT; ++j) {
        row[j]   = t + j * gstride;
        valid[j] = (row[j] < n);
        if (valid[j]) {
            float4 v = x4[row[j]];
            xv[j][0] = v.x; xv[j][1] = v.y; xv[j][2] = v.z; xv[j][3] = v.w;
            s1v[j]   = S1[row[j]];
        } else {
            xv[j][0] = xv[j][1] = xv[j][2] = xv[j][3] = 0.0f;
            s1v[j]   = 0.0f;
        }
    }
    uint64_t xp[2][4];
#pragma unroll
    for (int d = 0; d < 4; ++d) {
        xp[0][d] = pack2(xv[0][d], xv[1][d]);
        xp[1][d] = pack2(xv[2][d], xv[3][d]);
    }

    // HydroParam bounds: lows [100, 0.01, 0.01], highs [500, 100, 10]
    // sigmoid(y) = 0.5*tanh(0.5*y)+0.5  =>  val = (0.5*range)*tanh(0.5*y) + (0.5*range+low)
    const float halfrange[3] = {200.0f, 49.995f, 4.995f};
    const float midk[3]      = {300.0f, 50.005f, 5.005f};

    uint64_t val2[3][2];   // [param k][pair]

#pragma unroll
    for (int k = 0; k < 3; ++k) {
        // ---- layer 1: 4 -> 6, tanh ----
        uint64_t h1[2][6];
#pragma unroll
        for (int w = 0; w < 6; ++w) {
            uint64_t b = sb1[k * 6 + w];
            h1[0][w] = b; h1[1][w] = b;
        }
#pragma unroll
        for (int d = 0; d < 4; ++d) {
#pragma unroll
            for (int w = 0; w < 6; ++w) {
                uint64_t wt = sW1[k * 24 + d * 6 + w];
                h1[0][w] = fma2(xp[0][d], wt, h1[0][w]);
                h1[1][w] = fma2(xp[1][d], wt, h1[1][w]);
            }
        }
#pragma unroll
        for (int p = 0; p < 2; ++p)
#pragma unroll
            for (int w = 0; w < 6; ++w) h1[p][w] = tanh2(h1[p][w]);

        // ---- layer 2: 6 -> 6, tanh ----
        uint64_t h2[2][6];
#pragma unroll
        for (int v = 0; v < 6; ++v) {
            uint64_t b = sb2[k * 6 + v];
            h2[0][v] = b; h2[1][v] = b;
        }
#pragma unroll
        for (int w = 0; w < 6; ++w) {
#pragma unroll
            for (int v = 0; v < 6; ++v) {
                uint64_t wt = sW2[k * 36 + w * 6 + v];
                h2[0][v] = fma2(h1[0][w], wt, h2[0][v]);
                h2[1][v] = fma2(h1[1][w], wt, h2[1][v]);
            }
        }
#pragma unroll
        for (int p = 0; p < 2; ++p)
#pragma unroll
            for (int v = 0; v < 6; ++v) h2[p][v] = tanh2(h2[p][v]);

        // ---- layer 3: 6 -> 1 ----
        uint64_t y[2];
        {
            uint64_t b = sb3[k];
            y[0] = b; y[1] = b;
        }
#pragma unroll
        for (int v = 0; v < 6; ++v) {
            uint64_t wt = sW3[k * 6 + v];
            y[0] = fma2(h2[0][v], wt, y[0]);
            y[1] = fma2(h2[1][v], wt, y[1]);
        }

        // sigmoid-affine via tanh identity
        const uint64_t half2 = pack2(0.5f, 0.5f);
        const uint64_t hr2   = pack2(halfrange[k], halfrange[k]);
        const uint64_t mid2  = pack2(midk[k], midk[k]);
#pragma unroll
        for (int p = 0; p < 2; ++p) {
            uint64_t th = tanh2(mul2(y[p], half2));
            val2[k][p]  = fma2(th, hr2, mid2);
        }
    }

    // ---- hydrology term + clip (scalar epilogue) ----
#pragma unroll
    for (int p = 0; p < 2; ++p) {
        float S1max[2], ksv[2], nv[2];
        unpack2(val2[0][p], S1max[0], S1max[1]);
        unpack2(val2[1][p], ksv[0],   ksv[1]);
        unpack2(val2[2][p], nv[0],    nv[1]);
#pragma unroll
        for (int q = 0; q < 2; ++q) {
            const int j = 2 * p + q;
            if (valid[j]) {
                const float ratio = s1v[j] * rcp_fast(S1max[q]);
                float flow = ksv[q] * __powf(ratio, nv[q]);
                flow = fminf(flow, S1max[q]);
                flow = fmaxf(flow, 0.0f);
                out[row[j]] = flow;
            }
        }
    }
}

extern "C" void kernel_launch(void* const* d_in, const int* in_sizes, int n_in,
                              void* d_out, int out_size)
{
    const float* x  = (const float*)d_in[0];   // [N,4]
    const float* S1 = (const float*)d_in[1];   // [N,1]
    const float* W1 = (const float*)d_in[2];
    const float* b1 = (const float*)d_in[3];
    const float* W2 = (const float*)d_in[4];
    const float* b2 = (const float*)d_in[5];
    const float* W3 = (const float*)d_in[6];
    const float* b3 = (const float*)d_in[7];
    float* out = (float*)d_out;

    const int n = in_sizes[1];                 // S1 has N elements
    const int threads_needed = (n + RPT - 1) / RPT;
    const int blocks = (threads_needed + TPB - 1) / TPB;
    const int gstride = blocks * TPB;

    subsurface_flow_kernel<<<blocks, TPB>>>(
        (const float4*)x, S1, W1, b1, W2, b2, W3, b3, out, n, gstride);
}